// round 2
// baseline (speedup 1.0000x reference)
#include <cuda_runtime.h>

// Problem constants (fixed by the dataset).
static constexpr int BSZ = 16384;  // batch
static constexpr int HD  = 1024;   // hidden
static constexpr int DD  = 512;    // input/output feature dim

// Tiling.
static constexpr int BM = 64;   // rows (batch) per block
static constexpr int BN = 64;   // output cols per block
static constexpr int BK = 16;   // k-chunk
static constexpr int TM = 4;    // rows per thread
static constexpr int TN = 4;    // cols per thread
static constexpr int NTHREADS = (BM / TM) * (BN / TN);  // 256

// Scratch for intermediate hidden states (allocation-free contract: __device__ globals).
__device__ float g_h0[(size_t)BSZ * HD];
__device__ float g_h1[(size_t)BSZ * HD];

typedef unsigned long long u64;

// ---- packed f32x2 helpers (Blackwell packed-pair FMA: 2x fp32 throughput) ----
__device__ __forceinline__ u64 pack_dup(float a) {
    u64 r;
    unsigned ai = __float_as_uint(a);
    asm("mov.b64 %0, {%1, %1};" : "=l"(r) : "r"(ai));
    return r;
}
__device__ __forceinline__ void fma2(u64 &acc, u64 a, u64 b) {
    asm("fma.rn.f32x2 %0, %1, %2, %0;" : "+l"(acc) : "l"(a), "l"(b));
}
__device__ __forceinline__ float2 unpack2(u64 v) {
    unsigned lo, hi;
    asm("mov.b64 {%0, %1}, %2;" : "=r"(lo), "=r"(hi) : "l"(v));
    return make_float2(__uint_as_float(lo), __uint_as_float(hi));
}
__device__ __forceinline__ float sigm(float x) { return 1.0f / (1.0f + __expf(-x)); }

// One fused GEMM kernel.
//   LSTM=true : computes i/g/o gates (3 accumulators) of  A @ W_gateᵀ,
//               applies   h = sigmoid(i) ⊙ tanh  ... LSTM cell with zero state:
//               c = sigmoid(i)*tanh(g);  h = sigmoid(o)*tanh(c).
//               W rows: [0,H)=i, [H,2H)=f (DEAD, skipped), [2H,3H)=g, [3H,4H)=o.
//   LSTM=false: plain  A @ Wᵀ + b  (decoder).
// K  = reduction dim, NC = output row stride (= #output cols).
template<int K, int NC, bool LSTM>
__global__ __launch_bounds__(NTHREADS)
void gemm_kernel(const float* __restrict__ A, const float* __restrict__ W,
                 const float* __restrict__ b0, const float* __restrict__ b1,
                 float* __restrict__ out)
{
    constexpr int NG = LSTM ? 3 : 1;

    // Transposed tiles: As[k][m], Ws[g][k][n] -> contiguous float4 LDS reads.
    __shared__ __align__(16) float As[BK][BM];
    __shared__ __align__(16) float Ws[NG][BK][BN];

    const int tid  = threadIdx.x;
    const int tx   = tid & 15;     // col group 0..15
    const int ty   = tid >> 4;     // row group 0..15
    const int row0 = blockIdx.y * BM;
    const int col0 = blockIdx.x * BN;

    // Global-load mapping: one float4 per thread per tile.
    const int lrow = tid >> 2;           // 0..63
    const int lk   = (tid & 3) * 4;      // 0,4,8,12

    const float* aptr = A + (size_t)(row0 + lrow) * K + lk;
    const float* wptr[NG];
    wptr[0] = W + (size_t)(0 * HD + col0 + lrow) * K + lk;          // i (or decoder row)
    if constexpr (LSTM) {
        wptr[1] = W + (size_t)(2 * HD + col0 + lrow) * K + lk;      // g
        wptr[2] = W + (size_t)(3 * HD + col0 + lrow) * K + lk;      // o
    }

    u64 acc[NG][TM][TN / 2];
    #pragma unroll
    for (int g = 0; g < NG; g++)
        #pragma unroll
        for (int r = 0; r < TM; r++)
            #pragma unroll
            for (int p = 0; p < TN / 2; p++)
                acc[g][r][p] = 0ull;

    for (int k0 = 0; k0 < K; k0 += BK) {
        // Stage tiles (transposed stores).
        float4 av = *(const float4*)(aptr + k0);
        float4 wv[NG];
        #pragma unroll
        for (int g = 0; g < NG; g++) wv[g] = *(const float4*)(wptr[g] + k0);

        As[lk + 0][lrow] = av.x;
        As[lk + 1][lrow] = av.y;
        As[lk + 2][lrow] = av.z;
        As[lk + 3][lrow] = av.w;
        #pragma unroll
        for (int g = 0; g < NG; g++) {
            Ws[g][lk + 0][lrow] = wv[g].x;
            Ws[g][lk + 1][lrow] = wv[g].y;
            Ws[g][lk + 2][lrow] = wv[g].z;
            Ws[g][lk + 3][lrow] = wv[g].w;
        }
        __syncthreads();

        #pragma unroll
        for (int kk = 0; kk < BK; kk++) {
            float4 a4 = *(const float4*)&As[kk][ty * TM];
            u64 ad[TM];
            ad[0] = pack_dup(a4.x);
            ad[1] = pack_dup(a4.y);
            ad[2] = pack_dup(a4.z);
            ad[3] = pack_dup(a4.w);
            #pragma unroll
            for (int g = 0; g < NG; g++) {
                ulonglong2 w2 = *(const ulonglong2*)&Ws[g][kk][tx * TN];
                #pragma unroll
                for (int r = 0; r < TM; r++) {
                    fma2(acc[g][r][0], ad[r], w2.x);
                    fma2(acc[g][r][1], ad[r], w2.y);
                }
            }
        }
        __syncthreads();
    }

    // ---- Epilogue ----
    const int cbase = col0 + tx * TN;
    if constexpr (LSTM) {
        float bi[TN], bg[TN], bo[TN];
        #pragma unroll
        for (int j = 0; j < TN; j++) {
            int n = cbase + j;
            bi[j] = b0[n]          + b1[n];
            bg[j] = b0[2 * HD + n] + b1[2 * HD + n];
            bo[j] = b0[3 * HD + n] + b1[3 * HD + n];
        }
        #pragma unroll
        for (int r = 0; r < TM; r++) {
            int m = row0 + ty * TM + r;
            float h[TN];
            #pragma unroll
            for (int p = 0; p < TN / 2; p++) {
                float2 vi = unpack2(acc[0][r][p]);
                float2 vg = unpack2(acc[1][r][p]);
                float2 vo = unpack2(acc[2][r][p]);
                {
                    float iv = sigm(vi.x + bi[2 * p]);
                    float gv = tanhf(vg.x + bg[2 * p]);
                    float ov = sigm(vo.x + bo[2 * p]);
                    h[2 * p] = ov * tanhf(iv * gv);
                }
                {
                    float iv = sigm(vi.y + bi[2 * p + 1]);
                    float gv = tanhf(vg.y + bg[2 * p + 1]);
                    float ov = sigm(vo.y + bo[2 * p + 1]);
                    h[2 * p + 1] = ov * tanhf(iv * gv);
                }
            }
            *(float4*)&out[(size_t)m * NC + cbase] = make_float4(h[0], h[1], h[2], h[3]);
        }
    } else {
        float bb[TN];
        #pragma unroll
        for (int j = 0; j < TN; j++) bb[j] = b0[cbase + j];
        #pragma unroll
        for (int r = 0; r < TM; r++) {
            int m = row0 + ty * TM + r;
            float2 v0 = unpack2(acc[0][r][0]);
            float2 v1 = unpack2(acc[0][r][1]);
            *(float4*)&out[(size_t)m * NC + cbase] =
                make_float4(v0.x + bb[0], v0.y + bb[1], v1.x + bb[2], v1.y + bb[3]);
        }
    }
}

extern "C" void kernel_launch(void* const* d_in, const int* in_sizes, int n_in,
                              void* d_out, int out_size) {
    // metadata order: x, W_ih0, W_hh0, b_ih0, b_hh0, W_ih1, W_hh1, b_ih1, b_hh1, W_dec, b_dec
    const float* x     = (const float*)d_in[0];
    const float* W_ih0 = (const float*)d_in[1];
    // d_in[2] = W_hh0 : dead (h0 = 0)
    const float* b_ih0 = (const float*)d_in[3];
    const float* b_hh0 = (const float*)d_in[4];
    const float* W_ih1 = (const float*)d_in[5];
    // d_in[6] = W_hh1 : dead
    const float* b_ih1 = (const float*)d_in[7];
    const float* b_hh1 = (const float*)d_in[8];
    const float* W_dec = (const float*)d_in[9];
    const float* b_dec = (const float*)d_in[10];
    float* out = (float*)d_out;

    float *h0 = nullptr, *h1 = nullptr;
    cudaGetSymbolAddress((void**)&h0, g_h0);
    cudaGetSymbolAddress((void**)&h1, g_h1);

    dim3 blk(NTHREADS);
    dim3 g_lstm(HD / BN, BSZ / BM);   // 16 x 256
    dim3 g_dec(DD / BN, BSZ / BM);    // 8 x 256

    gemm_kernel<DD, HD, true ><<<g_lstm, blk>>>(x,  W_ih0, b_ih0, b_hh0, h0);
    gemm_kernel<HD, HD, true ><<<g_lstm, blk>>>(h0, W_ih1, b_ih1, b_hh1, h1);
    gemm_kernel<HD, DD, false><<<g_dec,  blk>>>(h1, W_dec, b_dec, nullptr, out);
}

// round 3
// speedup vs baseline: 1.0017x; 1.0017x over previous
#include <cuda_runtime.h>

// Problem constants (fixed by the dataset).
static constexpr int BSZ = 16384;  // batch
static constexpr int HD  = 1024;   // hidden
static constexpr int DD  = 512;    // input/output feature dim

// Tiling.
static constexpr int BM = 64;   // rows (batch) per block
static constexpr int BN = 64;   // output cols per block
static constexpr int BK = 16;   // k-chunk
static constexpr int TM = 4;    // rows per thread
static constexpr int TN = 4;    // cols per thread
static constexpr int NTHREADS = (BM / TM) * (BN / TN);  // 256

// Scratch for intermediate hidden states (allocation-free contract: __device__ globals).
__device__ float g_h0[(size_t)BSZ * HD];
__device__ float g_h1[(size_t)BSZ * HD];

typedef unsigned long long u64;

// ---- packed f32x2 helpers (Blackwell packed-pair FMA: 2x fp32 throughput) ----
__device__ __forceinline__ u64 pack_dup(float a) {
    u64 r;
    unsigned ai = __float_as_uint(a);
    asm("mov.b64 %0, {%1, %1};" : "=l"(r) : "r"(ai));
    return r;
}
__device__ __forceinline__ void fma2(u64 &acc, u64 a, u64 b) {
    asm("fma.rn.f32x2 %0, %1, %2, %0;" : "+l"(acc) : "l"(a), "l"(b));
}
__device__ __forceinline__ float2 unpack2(u64 v) {
    unsigned lo, hi;
    asm("mov.b64 {%0, %1}, %2;" : "=r"(lo), "=r"(hi) : "l"(v));
    return make_float2(__uint_as_float(lo), __uint_as_float(hi));
}
__device__ __forceinline__ float sigm(float x) { return 1.0f / (1.0f + __expf(-x)); }

// One fused GEMM kernel.
//   LSTM=true : computes i/g/o gates (3 accumulators) of  A @ W_gateᵀ,
//               applies   h = sigmoid(i) ⊙ tanh  ... LSTM cell with zero state:
//               c = sigmoid(i)*tanh(g);  h = sigmoid(o)*tanh(c).
//               W rows: [0,H)=i, [H,2H)=f (DEAD, skipped), [2H,3H)=g, [3H,4H)=o.
//   LSTM=false: plain  A @ Wᵀ + b  (decoder).
// K  = reduction dim, NC = output row stride (= #output cols).
template<int K, int NC, bool LSTM>
__global__ __launch_bounds__(NTHREADS)
void gemm_kernel(const float* __restrict__ A, const float* __restrict__ W,
                 const float* __restrict__ b0, const float* __restrict__ b1,
                 float* __restrict__ out)
{
    constexpr int NG = LSTM ? 3 : 1;

    // Transposed tiles: As[k][m], Ws[g][k][n] -> contiguous float4 LDS reads.
    __shared__ __align__(16) float As[BK][BM];
    __shared__ __align__(16) float Ws[NG][BK][BN];

    const int tid  = threadIdx.x;
    const int tx   = tid & 15;     // col group 0..15
    const int ty   = tid >> 4;     // row group 0..15
    const int row0 = blockIdx.y * BM;
    const int col0 = blockIdx.x * BN;

    // Global-load mapping: one float4 per thread per tile.
    const int lrow = tid >> 2;           // 0..63
    const int lk   = (tid & 3) * 4;      // 0,4,8,12

    const float* aptr = A + (size_t)(row0 + lrow) * K + lk;
    const float* wptr[NG];
    wptr[0] = W + (size_t)(0 * HD + col0 + lrow) * K + lk;          // i (or decoder row)
    if constexpr (LSTM) {
        wptr[1] = W + (size_t)(2 * HD + col0 + lrow) * K + lk;      // g
        wptr[2] = W + (size_t)(3 * HD + col0 + lrow) * K + lk;      // o
    }

    u64 acc[NG][TM][TN / 2];
    #pragma unroll
    for (int g = 0; g < NG; g++)
        #pragma unroll
        for (int r = 0; r < TM; r++)
            #pragma unroll
            for (int p = 0; p < TN / 2; p++)
                acc[g][r][p] = 0ull;

    for (int k0 = 0; k0 < K; k0 += BK) {
        // Stage tiles (transposed stores).
        float4 av = *(const float4*)(aptr + k0);
        float4 wv[NG];
        #pragma unroll
        for (int g = 0; g < NG; g++) wv[g] = *(const float4*)(wptr[g] + k0);

        As[lk + 0][lrow] = av.x;
        As[lk + 1][lrow] = av.y;
        As[lk + 2][lrow] = av.z;
        As[lk + 3][lrow] = av.w;
        #pragma unroll
        for (int g = 0; g < NG; g++) {
            Ws[g][lk + 0][lrow] = wv[g].x;
            Ws[g][lk + 1][lrow] = wv[g].y;
            Ws[g][lk + 2][lrow] = wv[g].z;
            Ws[g][lk + 3][lrow] = wv[g].w;
        }
        __syncthreads();

        #pragma unroll
        for (int kk = 0; kk < BK; kk++) {
            float4 a4 = *(const float4*)&As[kk][ty * TM];
            u64 ad[TM];
            ad[0] = pack_dup(a4.x);
            ad[1] = pack_dup(a4.y);
            ad[2] = pack_dup(a4.z);
            ad[3] = pack_dup(a4.w);
            #pragma unroll
            for (int g = 0; g < NG; g++) {
                ulonglong2 w2 = *(const ulonglong2*)&Ws[g][kk][tx * TN];
                #pragma unroll
                for (int r = 0; r < TM; r++) {
                    fma2(acc[g][r][0], ad[r], w2.x);
                    fma2(acc[g][r][1], ad[r], w2.y);
                }
            }
        }
        __syncthreads();
    }

    // ---- Epilogue ----
    const int cbase = col0 + tx * TN;
    if constexpr (LSTM) {
        float bi[TN], bg[TN], bo[TN];
        #pragma unroll
        for (int j = 0; j < TN; j++) {
            int n = cbase + j;
            bi[j] = b0[n]          + b1[n];
            bg[j] = b0[2 * HD + n] + b1[2 * HD + n];
            bo[j] = b0[3 * HD + n] + b1[3 * HD + n];
        }
        #pragma unroll
        for (int r = 0; r < TM; r++) {
            int m = row0 + ty * TM + r;
            float h[TN];
            #pragma unroll
            for (int p = 0; p < TN / 2; p++) {
                float2 vi = unpack2(acc[0][r][p]);
                float2 vg = unpack2(acc[1][r][p]);
                float2 vo = unpack2(acc[2][r][p]);
                {
                    float iv = sigm(vi.x + bi[2 * p]);
                    float gv = tanhf(vg.x + bg[2 * p]);
                    float ov = sigm(vo.x + bo[2 * p]);
                    h[2 * p] = ov * tanhf(iv * gv);
                }
                {
                    float iv = sigm(vi.y + bi[2 * p + 1]);
                    float gv = tanhf(vg.y + bg[2 * p + 1]);
                    float ov = sigm(vo.y + bo[2 * p + 1]);
                    h[2 * p + 1] = ov * tanhf(iv * gv);
                }
            }
            *(float4*)&out[(size_t)m * NC + cbase] = make_float4(h[0], h[1], h[2], h[3]);
        }
    } else {
        float bb[TN];
        #pragma unroll
        for (int j = 0; j < TN; j++) bb[j] = b0[cbase + j];
        #pragma unroll
        for (int r = 0; r < TM; r++) {
            int m = row0 + ty * TM + r;
            float2 v0 = unpack2(acc[0][r][0]);
            float2 v1 = unpack2(acc[0][r][1]);
            *(float4*)&out[(size_t)m * NC + cbase] =
                make_float4(v0.x + bb[0], v0.y + bb[1], v1.x + bb[2], v1.y + bb[3]);
        }
    }
}

extern "C" void kernel_launch(void* const* d_in, const int* in_sizes, int n_in,
                              void* d_out, int out_size) {
    // metadata order: x, W_ih0, W_hh0, b_ih0, b_hh0, W_ih1, W_hh1, b_ih1, b_hh1, W_dec, b_dec
    const float* x     = (const float*)d_in[0];
    const float* W_ih0 = (const float*)d_in[1];
    // d_in[2] = W_hh0 : dead (h0 = 0)
    const float* b_ih0 = (const float*)d_in[3];
    const float* b_hh0 = (const float*)d_in[4];
    const float* W_ih1 = (const float*)d_in[5];
    // d_in[6] = W_hh1 : dead
    const float* b_ih1 = (const float*)d_in[7];
    const float* b_hh1 = (const float*)d_in[8];
    const float* W_dec = (const float*)d_in[9];
    const float* b_dec = (const float*)d_in[10];
    float* out = (float*)d_out;

    float *h0 = nullptr, *h1 = nullptr;
    cudaGetSymbolAddress((void**)&h0, g_h0);
    cudaGetSymbolAddress((void**)&h1, g_h1);

    dim3 blk(NTHREADS);
    dim3 g_lstm(HD / BN, BSZ / BM);   // 16 x 256
    dim3 g_dec(DD / BN, BSZ / BM);    // 8 x 256

    gemm_kernel<DD, HD, true ><<<g_lstm, blk>>>(x,  W_ih0, b_ih0, b_hh0, h0);
    gemm_kernel<HD, HD, true ><<<g_lstm, blk>>>(h0, W_ih1, b_ih1, b_hh1, h1);
    gemm_kernel<HD, DD, false><<<g_dec,  blk>>>(h1, W_dec, b_dec, nullptr, out);
}

// round 7
// speedup vs baseline: 3.6332x; 3.6270x over previous
#include <cuda_runtime.h>
#include <cuda_fp16.h>
#include <cstdint>

static constexpr int BSZ = 16384;
static constexpr int HD  = 1024;
static constexpr int DD  = 512;
static constexpr float WSCALE  = 32.0f;
static constexpr float IWSCALE = 1.0f / 32.0f;

// ---------------- device scratch (allocation-free contract) ----------------
__device__ __align__(256) __half g_x_h [(size_t)BSZ * DD];
__device__ __align__(256) __half g_h0_h[(size_t)BSZ * HD];
__device__ __align__(256) __half g_h1_h[(size_t)BSZ * HD];
__device__ __align__(256) __half g_w0_hi[(size_t)4 * HD * DD];
__device__ __align__(256) __half g_w0_lo[(size_t)4 * HD * DD];
__device__ __align__(256) __half g_w1_hi[(size_t)4 * HD * HD];
__device__ __align__(256) __half g_w1_lo[(size_t)4 * HD * HD];
__device__ __align__(256) __half g_wd_hi[(size_t)DD * HD];
__device__ __align__(256) __half g_wd_lo[(size_t)DD * HD];

// ---------------- helpers ----------------
__device__ __forceinline__ uint32_t smem_u32(const void* p) {
    uint32_t a;
    asm("{ .reg .u64 t; cvta.to.shared.u64 t, %1; cvt.u32.u64 %0, t; }" : "=r"(a) : "l"(p));
    return a;
}
__device__ __forceinline__ void cpa16(uint32_t dst, const void* src) {
    asm volatile("cp.async.cg.shared.global [%0], [%1], 16;\n" :: "r"(dst), "l"(src));
}
__device__ __forceinline__ void ldsm4(uint32_t* r, uint32_t a) {
    asm volatile("ldmatrix.sync.aligned.m8n8.x4.shared.b16 {%0,%1,%2,%3}, [%4];"
        : "=r"(r[0]), "=r"(r[1]), "=r"(r[2]), "=r"(r[3]) : "r"(a));
}
__device__ __forceinline__ void mma16816(float* d, const uint32_t* a, const uint32_t* b) {
    asm volatile("mma.sync.aligned.m16n8k16.row.col.f32.f16.f16.f32 "
        "{%0,%1,%2,%3}, {%4,%5,%6,%7}, {%8,%9}, {%0,%1,%2,%3};"
        : "+f"(d[0]), "+f"(d[1]), "+f"(d[2]), "+f"(d[3])
        : "r"(a[0]), "r"(a[1]), "r"(a[2]), "r"(a[3]), "r"(b[0]), "r"(b[1]));
}
__device__ __forceinline__ float sigm(float x) { return 1.0f / (1.0f + __expf(-x)); }
__device__ __forceinline__ float tanh_e(float x) {
    float ax = fabsf(x);
    float e  = __expf(2.0f * ax);
    float t  = 1.0f - 2.0f / (1.0f + e);
    return copysignf(t, x);
}

// ---------------- conversion kernels ----------------
__global__ void cvt_h_kernel(const float4* __restrict__ src, __half2* __restrict__ dst, int n4) {
    int i = blockIdx.x * blockDim.x + threadIdx.x;
    if (i >= n4) return;
    float4 v = src[i];
    dst[2 * i + 0] = __floats2half2_rn(v.x, v.y);
    dst[2 * i + 1] = __floats2half2_rn(v.z, v.w);
}
__global__ void cvt_split_kernel(const float4* __restrict__ src,
                                 __half2* __restrict__ hi, __half2* __restrict__ lo, int n4) {
    int i = blockIdx.x * blockDim.x + threadIdx.x;
    if (i >= n4) return;
    float4 v = src[i];
    float sx = v.x * WSCALE, sy = v.y * WSCALE, sz = v.z * WSCALE, sw = v.w * WSCALE;
    __half hx = __float2half_rn(sx), hy = __float2half_rn(sy);
    __half hz = __float2half_rn(sz), hw = __float2half_rn(sw);
    __half2 h0; h0.x = hx; h0.y = hy;
    __half2 h1; h1.x = hz; h1.y = hw;
    __half2 l0 = __floats2half2_rn(sx - __half2float(hx), sy - __half2float(hy));
    __half2 l1 = __floats2half2_rn(sz - __half2float(hz), sw - __half2float(hw));
    hi[2 * i + 0] = h0; hi[2 * i + 1] = h1;
    lo[2 * i + 0] = l0; lo[2 * i + 1] = l1;
}

// ---------------- fused mma.sync GEMM ----------------
// NG==3: gates i/g/o of A @ W^T (f-gate dead), LSTM-cell epilogue -> h (fp16).
// NG==1: decoder A @ W^T + b -> fp32.
// W supplied as scaled (x32) hi/lo fp16 split; acc * (1/32) in epilogue.
template<int K, int NG, int NT>
__global__ void __launch_bounds__(256, 1)
mm_kernel(const __half* __restrict__ Ah,
          const __half* __restrict__ Whi, const __half* __restrict__ Wlo,
          const float* __restrict__ b0, const float* __restrict__ b1,
          float* __restrict__ outF, __half* __restrict__ outH)
{
    constexpr int PITCH  = 144;              // 64 fp16 + 8 pad -> ldmatrix conflict-free
    constexpr int ASZ    = 128 * PITCH;
    constexpr int WSZ    = NT * PITCH;
    constexpr int STAGE  = ASZ + NG * 2 * WSZ;
    constexpr int NCHUNK = K / 64;
    constexpr int NFRAG  = NT / 16;          // n8 frags per warp per gate (warp spans NT/2)
    constexpr int NPAIR  = NFRAG / 2;

    extern __shared__ char smem[];
    const uint32_t sb = smem_u32(smem);
    float* bs = (float*)(smem + 2 * STAGE);

    const int tid = threadIdx.x, wid = tid >> 5, lane = tid & 31;
    const int wm = wid & 3, wn = wid >> 2;
    const int row0 = blockIdx.y * 128, col0 = blockIdx.x * NT;

    // bias sums -> smem
    for (int i = tid; i < NG * NT; i += 256) {
        int g = i / NT, n = i - g * NT;
        int go = (NG == 3) ? ((g == 0) ? 0 : (g == 1 ? 2 * HD : 3 * HD)) : 0;
        float bv = b0[go + col0 + n];
        if (NG == 3) bv += b1[go + col0 + n];
        bs[i] = bv;
    }

    const int lr = tid >> 3;     // 0..31 row within 32-row slab
    const int lc = tid & 7;      // 16B chunk within 64-fp16 row

    auto load_chunk = [&](int s, int ck) {
        const int k0 = ck * 64;
        const uint32_t st = sb + s * STAGE;
        #pragma unroll
        for (int it = 0; it < 4; it++) {
            int r = lr + it * 32;
            cpa16(st + r * PITCH + lc * 16, Ah + (size_t)(row0 + r) * K + k0 + lc * 8);
        }
        #pragma unroll
        for (int g = 0; g < NG; g++) {
            const int go = (NG == 3) ? ((g == 0) ? 0 : (g == 1 ? 2 * HD : 3 * HD)) : 0;
            #pragma unroll
            for (int h = 0; h < 2; h++) {
                const __half* wsrc = h ? Wlo : Whi;
                uint32_t wb = st + ASZ + (g * 2 + h) * WSZ;
                #pragma unroll
                for (int it = 0; it < NT / 32; it++) {
                    int r = lr + it * 32;
                    cpa16(wb + r * PITCH + lc * 16,
                          wsrc + (size_t)(go + col0 + r) * K + k0 + lc * 8);
                }
            }
        }
        asm volatile("cp.async.commit_group;" ::: "memory");
    };

    // ldmatrix per-lane base offsets
    uint32_t aOff[2];
    #pragma unroll
    for (int f = 0; f < 2; f++)
        aOff[f] = (uint32_t)((wm * 32 + f * 16 + (lane & 15)) * PITCH + (lane >> 4) * 16);
    // B (weights): W stored [n][k] -> 8x8 blocks have n as rows; NON-trans ldmatrix
    // yields lane l -> (n = l/4, k = 2*(l%4)) which is exactly the mma B fragment.
    uint32_t bOff[NPAIR];
    #pragma unroll
    for (int p = 0; p < NPAIR; p++)
        bOff[p] = (uint32_t)((wn * (NT / 2) + p * 16 + (lane & 7) + ((lane >> 4) & 1) * 8) * PITCH
                             + ((lane >> 3) & 1) * 16);

    float acc[NG][2][NFRAG][4];
    #pragma unroll
    for (int g = 0; g < NG; g++)
        #pragma unroll
        for (int f = 0; f < 2; f++)
            #pragma unroll
            for (int j = 0; j < NFRAG; j++)
                #pragma unroll
                for (int q = 0; q < 4; q++) acc[g][f][j][q] = 0.0f;

    load_chunk(0, 0);
    load_chunk(1, 1);

    for (int k = 0; k < NCHUNK; k++) {
        const int s = k & 1;
        if (k + 1 < NCHUNK) asm volatile("cp.async.wait_group 1;" ::: "memory");
        else                asm volatile("cp.async.wait_group 0;" ::: "memory");
        __syncthreads();

        const uint32_t st = sb + s * STAGE;
        #pragma unroll
        for (int ks = 0; ks < 4; ks++) {
            uint32_t aF[2][4];
            ldsm4(aF[0], st + aOff[0] + ks * 32);
            ldsm4(aF[1], st + aOff[1] + ks * 32);
            #pragma unroll
            for (int g = 0; g < NG; g++) {
                const uint32_t wb = st + ASZ + g * 2 * WSZ;
                uint32_t bh[NPAIR][4], bl[NPAIR][4];
                #pragma unroll
                for (int p = 0; p < NPAIR; p++) {
                    ldsm4(bh[p], wb + bOff[p] + ks * 32);
                    ldsm4(bl[p], wb + WSZ + bOff[p] + ks * 32);
                }
                #pragma unroll
                for (int f = 0; f < 2; f++)
                    #pragma unroll
                    for (int j = 0; j < NFRAG; j++)
                        mma16816(acc[g][f][j], aF[f], &bh[j >> 1][(j & 1) * 2]);
                #pragma unroll
                for (int f = 0; f < 2; f++)
                    #pragma unroll
                    for (int j = 0; j < NFRAG; j++)
                        mma16816(acc[g][f][j], aF[f], &bl[j >> 1][(j & 1) * 2]);
            }
        }
        __syncthreads();
        if (k + 2 < NCHUNK) load_chunk(s, k + 2);
    }

    // ---------------- epilogue ----------------
    const int mBase = row0 + wm * 32 + (lane >> 2);
    const int nLoc0 = wn * (NT / 2) + (lane & 3) * 2;      // col offset within tile

    if constexpr (NG == 3) {
        #pragma unroll
        for (int f = 0; f < 2; f++)
            #pragma unroll
            for (int j = 0; j < NFRAG; j++)
                #pragma unroll
                for (int hh = 0; hh < 2; hh++) {
                    int m = mBase + f * 16 + hh * 8;
                    int nl = nLoc0 + j * 8;
                    float h2[2];
                    #pragma unroll
                    for (int u = 0; u < 2; u++) {
                        float iv = sigm(acc[0][f][j][hh * 2 + u] * IWSCALE + bs[0 * NT + nl + u]);
                        float gv = tanh_e(acc[1][f][j][hh * 2 + u] * IWSCALE + bs[1 * NT + nl + u]);
                        float ov = sigm(acc[2][f][j][hh * 2 + u] * IWSCALE + bs[2 * NT + nl + u]);
                        h2[u] = ov * tanh_e(iv * gv);
                    }
                    *(__half2*)(outH + (size_t)m * HD + col0 + nl) = __floats2half2_rn(h2[0], h2[1]);
                }
    } else {
        #pragma unroll
        for (int f = 0; f < 2; f++)
            #pragma unroll
            for (int j = 0; j < NFRAG; j++)
                #pragma unroll
                for (int hh = 0; hh < 2; hh++) {
                    int m = mBase + f * 16 + hh * 8;
                    int nl = nLoc0 + j * 8;
                    float2 v;
                    v.x = acc[0][f][j][hh * 2 + 0] * IWSCALE + bs[nl + 0];
                    v.y = acc[0][f][j][hh * 2 + 1] * IWSCALE + bs[nl + 1];
                    *(float2*)(outF + (size_t)m * DD + col0 + nl) = v;
                }
    }
}

// ---------------- launch ----------------
extern "C" void kernel_launch(void* const* d_in, const int* in_sizes, int n_in,
                              void* d_out, int out_size) {
    const float* x     = (const float*)d_in[0];
    const float* W_ih0 = (const float*)d_in[1];
    const float* b_ih0 = (const float*)d_in[3];
    const float* b_hh0 = (const float*)d_in[4];
    const float* W_ih1 = (const float*)d_in[5];
    const float* b_ih1 = (const float*)d_in[7];
    const float* b_hh1 = (const float*)d_in[8];
    const float* W_dec = (const float*)d_in[9];
    const float* b_dec = (const float*)d_in[10];
    float* out = (float*)d_out;

    __half *xh, *h0h, *h1h, *w0hi, *w0lo, *w1hi, *w1lo, *wdhi, *wdlo;
    cudaGetSymbolAddress((void**)&xh,   g_x_h);
    cudaGetSymbolAddress((void**)&h0h,  g_h0_h);
    cudaGetSymbolAddress((void**)&h1h,  g_h1_h);
    cudaGetSymbolAddress((void**)&w0hi, g_w0_hi); cudaGetSymbolAddress((void**)&w0lo, g_w0_lo);
    cudaGetSymbolAddress((void**)&w1hi, g_w1_hi); cudaGetSymbolAddress((void**)&w1lo, g_w1_lo);
    cudaGetSymbolAddress((void**)&wdhi, g_wd_hi); cudaGetSymbolAddress((void**)&wdlo, g_wd_lo);

    // shared-memory sizes
    constexpr int PITCH = 144;
    constexpr int STAGE_L = 128 * PITCH + 3 * 2 * 64 * PITCH;    // 73728
    constexpr int STAGE_D = 128 * PITCH + 1 * 2 * 128 * PITCH;   // 55296
    constexpr int SM_L = 2 * STAGE_L + 3 * 64 * 4;               // 148224
    constexpr int SM_D = 2 * STAGE_D + 1 * 128 * 4;              // 111104
    cudaFuncSetAttribute(mm_kernel<DD, 3, 64>,  cudaFuncAttributeMaxDynamicSharedMemorySize, SM_L);
    cudaFuncSetAttribute(mm_kernel<HD, 3, 64>,  cudaFuncAttributeMaxDynamicSharedMemorySize, SM_L);
    cudaFuncSetAttribute(mm_kernel<HD, 1, 128>, cudaFuncAttributeMaxDynamicSharedMemorySize, SM_D);

    // conversions
    {
        int n4 = (int)((size_t)BSZ * DD / 4);
        cvt_h_kernel<<<(n4 + 255) / 256, 256>>>((const float4*)x, (__half2*)xh, n4);
    }
    auto split = [&](const float* src, __half* hi, __half* lo, size_t n) {
        int n4 = (int)(n / 4);
        cvt_split_kernel<<<(n4 + 255) / 256, 256>>>((const float4*)src, (__half2*)hi, (__half2*)lo, n4);
    };
    split(W_ih0, w0hi, w0lo, (size_t)4 * HD * DD);
    split(W_ih1, w1hi, w1lo, (size_t)4 * HD * HD);
    split(W_dec, wdhi, wdlo, (size_t)DD * HD);

    dim3 blk(256);
    dim3 gL(HD / 64, BSZ / 128);    // 16 x 128
    dim3 gD(DD / 128, BSZ / 128);   // 4  x 128

    mm_kernel<DD, 3, 64><<<gL, blk, SM_L>>>(xh,  w0hi, w0lo, b_ih0, b_hh0, nullptr, h0h);
    mm_kernel<HD, 3, 64><<<gL, blk, SM_L>>>(h0h, w1hi, w1lo, b_ih1, b_hh1, nullptr, h1h);
    mm_kernel<HD, 1, 128><<<gD, blk, SM_D>>>(h1h, wdhi, wdlo, b_dec, nullptr, out, nullptr);
}

// round 8
// speedup vs baseline: 5.1802x; 1.4258x over previous
#include <cuda_runtime.h>
#include <cuda_fp16.h>
#include <cstdint>

static constexpr int BSZ = 16384;
static constexpr int HD  = 1024;
static constexpr int DD  = 512;

// ---------------- device scratch (allocation-free contract) ----------------
__device__ __align__(256) __half g_x_h [(size_t)BSZ * DD];
__device__ __align__(256) __half g_h0_h[(size_t)BSZ * HD];
__device__ __align__(256) __half g_h1_h[(size_t)BSZ * HD];
__device__ __align__(256) __half g_w0_h[(size_t)4 * HD * DD];
__device__ __align__(256) __half g_w1_h[(size_t)4 * HD * HD];
__device__ __align__(256) __half g_wd_h[(size_t)DD * HD];

// ---------------- helpers ----------------
__device__ __forceinline__ uint32_t smem_u32(const void* p) {
    uint32_t a;
    asm("{ .reg .u64 t; cvta.to.shared.u64 t, %1; cvt.u32.u64 %0, t; }" : "=r"(a) : "l"(p));
    return a;
}
__device__ __forceinline__ void cpa16(uint32_t dst, const void* src) {
    asm volatile("cp.async.cg.shared.global [%0], [%1], 16;\n" :: "r"(dst), "l"(src));
}
__device__ __forceinline__ void ldsm4(uint32_t* r, uint32_t a) {
    asm volatile("ldmatrix.sync.aligned.m8n8.x4.shared.b16 {%0,%1,%2,%3}, [%4];"
        : "=r"(r[0]), "=r"(r[1]), "=r"(r[2]), "=r"(r[3]) : "r"(a));
}
__device__ __forceinline__ void mma16816(float* d, const uint32_t* a, const uint32_t* b) {
    asm volatile("mma.sync.aligned.m16n8k16.row.col.f32.f16.f16.f32 "
        "{%0,%1,%2,%3}, {%4,%5,%6,%7}, {%8,%9}, {%0,%1,%2,%3};"
        : "+f"(d[0]), "+f"(d[1]), "+f"(d[2]), "+f"(d[3])
        : "r"(a[0]), "r"(a[1]), "r"(a[2]), "r"(a[3]), "r"(b[0]), "r"(b[1]));
}
__device__ __forceinline__ float sigm(float x) { return 1.0f / (1.0f + __expf(-x)); }
__device__ __forceinline__ float tanh_e(float x) {
    float ax = fabsf(x);
    float e  = __expf(2.0f * ax);
    float t  = 1.0f - 2.0f / (1.0f + e);
    return copysignf(t, x);
}

// ---------------- fp32 -> fp16 conversion ----------------
__global__ void cvt_h_kernel(const float4* __restrict__ src, __half2* __restrict__ dst, int n4) {
    int i = blockIdx.x * blockDim.x + threadIdx.x;
    if (i >= n4) return;
    float4 v = src[i];
    dst[2 * i + 0] = __floats2half2_rn(v.x, v.y);
    dst[2 * i + 1] = __floats2half2_rn(v.z, v.w);
}

// ---------------- fused mma.sync GEMM (single fp16 pass) ----------------
// NG==3: gates i/g/o of A @ W^T (f-gate dead), LSTM-cell epilogue -> h (fp16).
// NG==1: decoder A @ W^T + b -> fp32.
template<int K, int NG, int NT>
__global__ void __launch_bounds__(256, 1)
mm_kernel(const __half* __restrict__ Ah, const __half* __restrict__ Wh,
          const float* __restrict__ b0, const float* __restrict__ b1,
          float* __restrict__ outF, __half* __restrict__ outH)
{
    constexpr int PITCH  = 144;              // 64 fp16 + 8 pad -> ldmatrix conflict-free
    constexpr int ASZ    = 128 * PITCH;
    constexpr int WSZ    = NT * PITCH;
    constexpr int STAGE  = ASZ + NG * WSZ;
    constexpr int NCHUNK = K / 64;
    constexpr int NFRAG  = NT / 16;          // n8 frags per warp per gate (warp spans NT/2)
    constexpr int NPAIR  = NFRAG / 2;

    extern __shared__ char smem[];
    const uint32_t sb = smem_u32(smem);
    float* bs = (float*)(smem + 2 * STAGE);

    const int tid = threadIdx.x, wid = tid >> 5, lane = tid & 31;
    const int wm = wid & 3, wn = wid >> 2;
    const int row0 = blockIdx.y * 128, col0 = blockIdx.x * NT;

    // bias sums -> smem
    for (int i = tid; i < NG * NT; i += 256) {
        int g = i / NT, n = i - g * NT;
        int go = (NG == 3) ? ((g == 0) ? 0 : (g == 1 ? 2 * HD : 3 * HD)) : 0;
        float bv = b0[go + col0 + n];
        if (NG == 3) bv += b1[go + col0 + n];
        bs[i] = bv;
    }

    const int lr = tid >> 3;     // 0..31 row within 32-row slab
    const int lc = tid & 7;      // 16B chunk within 64-fp16 row

    auto load_chunk = [&](int s, int ck) {
        const int k0 = ck * 64;
        const uint32_t st = sb + s * STAGE;
        #pragma unroll
        for (int it = 0; it < 4; it++) {
            int r = lr + it * 32;
            cpa16(st + r * PITCH + lc * 16, Ah + (size_t)(row0 + r) * K + k0 + lc * 8);
        }
        #pragma unroll
        for (int g = 0; g < NG; g++) {
            const int go = (NG == 3) ? ((g == 0) ? 0 : (g == 1 ? 2 * HD : 3 * HD)) : 0;
            uint32_t wb = st + ASZ + g * WSZ;
            #pragma unroll
            for (int it = 0; it < NT / 32; it++) {
                int r = lr + it * 32;
                cpa16(wb + r * PITCH + lc * 16,
                      Wh + (size_t)(go + col0 + r) * K + k0 + lc * 8);
            }
        }
        asm volatile("cp.async.commit_group;" ::: "memory");
    };

    // ldmatrix per-lane base offsets.
    uint32_t aOff[2];
    #pragma unroll
    for (int f = 0; f < 2; f++)
        aOff[f] = (uint32_t)((wm * 32 + f * 16 + (lane & 15)) * PITCH + (lane >> 4) * 16);
    // W stored [n][k] -> non-trans ldmatrix gives exactly the B fragment (n = l/4, k = 2*(l%4)).
    uint32_t bOff[NPAIR];
    #pragma unroll
    for (int p = 0; p < NPAIR; p++)
        bOff[p] = (uint32_t)((wn * (NT / 2) + p * 16 + (lane & 7) + ((lane >> 4) & 1) * 8) * PITCH
                             + ((lane >> 3) & 1) * 16);

    float acc[NG][2][NFRAG][4];
    #pragma unroll
    for (int g = 0; g < NG; g++)
        #pragma unroll
        for (int f = 0; f < 2; f++)
            #pragma unroll
            for (int j = 0; j < NFRAG; j++)
                #pragma unroll
                for (int q = 0; q < 4; q++) acc[g][f][j][q] = 0.0f;

    load_chunk(0, 0);
    load_chunk(1, 1);

    for (int k = 0; k < NCHUNK; k++) {
        const int s = k & 1;
        if (k + 1 < NCHUNK) asm volatile("cp.async.wait_group 1;" ::: "memory");
        else                asm volatile("cp.async.wait_group 0;" ::: "memory");
        __syncthreads();

        const uint32_t st = sb + s * STAGE;
        #pragma unroll
        for (int ks = 0; ks < 4; ks++) {
            uint32_t aF[2][4];
            ldsm4(aF[0], st + aOff[0] + ks * 32);
            ldsm4(aF[1], st + aOff[1] + ks * 32);
            #pragma unroll
            for (int g = 0; g < NG; g++) {
                const uint32_t wb = st + ASZ + g * WSZ;
                uint32_t bh[NPAIR][4];
                #pragma unroll
                for (int p = 0; p < NPAIR; p++)
                    ldsm4(bh[p], wb + bOff[p] + ks * 32);
                #pragma unroll
                for (int f = 0; f < 2; f++)
                    #pragma unroll
                    for (int j = 0; j < NFRAG; j++)
                        mma16816(acc[g][f][j], aF[f], &bh[j >> 1][(j & 1) * 2]);
            }
        }
        __syncthreads();
        if (k + 2 < NCHUNK) load_chunk(s, k + 2);
    }

    // ---------------- epilogue ----------------
    const int mBase = row0 + wm * 32 + (lane >> 2);
    const int nLoc0 = wn * (NT / 2) + (lane & 3) * 2;      // col offset within tile

    if constexpr (NG == 3) {
        #pragma unroll
        for (int f = 0; f < 2; f++)
            #pragma unroll
            for (int j = 0; j < NFRAG; j++)
                #pragma unroll
                for (int hh = 0; hh < 2; hh++) {
                    int m = mBase + f * 16 + hh * 8;
                    int nl = nLoc0 + j * 8;
                    float h2[2];
                    #pragma unroll
                    for (int u = 0; u < 2; u++) {
                        float iv = sigm(acc[0][f][j][hh * 2 + u] + bs[0 * NT + nl + u]);
                        float gv = tanh_e(acc[1][f][j][hh * 2 + u] + bs[1 * NT + nl + u]);
                        float ov = sigm(acc[2][f][j][hh * 2 + u] + bs[2 * NT + nl + u]);
                        h2[u] = ov * tanh_e(iv * gv);
                    }
                    *(__half2*)(outH + (size_t)m * HD + col0 + nl) = __floats2half2_rn(h2[0], h2[1]);
                }
    } else {
        #pragma unroll
        for (int f = 0; f < 2; f++)
            #pragma unroll
            for (int j = 0; j < NFRAG; j++)
                #pragma unroll
                for (int hh = 0; hh < 2; hh++) {
                    int m = mBase + f * 16 + hh * 8;
                    int nl = nLoc0 + j * 8;
                    float2 v;
                    v.x = acc[0][f][j][hh * 2 + 0] + bs[nl + 0];
                    v.y = acc[0][f][j][hh * 2 + 1] + bs[nl + 1];
                    *(float2*)(outF + (size_t)m * DD + col0 + nl) = v;
                }
    }
}

// ---------------- launch ----------------
extern "C" void kernel_launch(void* const* d_in, const int* in_sizes, int n_in,
                              void* d_out, int out_size) {
    const float* x     = (const float*)d_in[0];
    const float* W_ih0 = (const float*)d_in[1];
    const float* b_ih0 = (const float*)d_in[3];
    const float* b_hh0 = (const float*)d_in[4];
    const float* W_ih1 = (const float*)d_in[5];
    const float* b_ih1 = (const float*)d_in[7];
    const float* b_hh1 = (const float*)d_in[8];
    const float* W_dec = (const float*)d_in[9];
    const float* b_dec = (const float*)d_in[10];
    float* out = (float*)d_out;

    __half *xh, *h0h, *h1h, *w0h, *w1h, *wdh;
    cudaGetSymbolAddress((void**)&xh,  g_x_h);
    cudaGetSymbolAddress((void**)&h0h, g_h0_h);
    cudaGetSymbolAddress((void**)&h1h, g_h1_h);
    cudaGetSymbolAddress((void**)&w0h, g_w0_h);
    cudaGetSymbolAddress((void**)&w1h, g_w1_h);
    cudaGetSymbolAddress((void**)&wdh, g_wd_h);

    // shared-memory sizes
    constexpr int PITCH = 144;
    constexpr int STAGE_L = 128 * PITCH + 3 * 64 * PITCH;     // 46080
    constexpr int STAGE_D = 128 * PITCH + 1 * 128 * PITCH;    // 36864
    constexpr int SM_L = 2 * STAGE_L + 3 * 64 * 4;            // 92928
    constexpr int SM_D = 2 * STAGE_D + 1 * 128 * 4;           // 74240
    cudaFuncSetAttribute(mm_kernel<DD, 3, 64>,  cudaFuncAttributeMaxDynamicSharedMemorySize, SM_L);
    cudaFuncSetAttribute(mm_kernel<HD, 3, 64>,  cudaFuncAttributeMaxDynamicSharedMemorySize, SM_L);
    cudaFuncSetAttribute(mm_kernel<HD, 1, 128>, cudaFuncAttributeMaxDynamicSharedMemorySize, SM_D);

    // conversions (all plain fp16 now)
    auto cvt = [&](const float* src, __half* dst, size_t n) {
        int n4 = (int)(n / 4);
        cvt_h_kernel<<<(n4 + 255) / 256, 256>>>((const float4*)src, (__half2*)dst, n4);
    };
    cvt(x,     xh,  (size_t)BSZ * DD);
    cvt(W_ih0, w0h, (size_t)4 * HD * DD);
    cvt(W_ih1, w1h, (size_t)4 * HD * HD);
    cvt(W_dec, wdh, (size_t)DD * HD);

    dim3 blk(256);
    dim3 gL(HD / 64, BSZ / 128);    // 16 x 128
    dim3 gD(DD / 128, BSZ / 128);   // 4  x 128

    mm_kernel<DD, 3, 64><<<gL, blk, SM_L>>>(xh,  w0h, b_ih0, b_hh0, nullptr, h0h);
    mm_kernel<HD, 3, 64><<<gL, blk, SM_L>>>(h0h, w1h, b_ih1, b_hh1, nullptr, h1h);
    mm_kernel<HD, 1, 128><<<gD, blk, SM_D>>>(h1h, wdh, b_dec, nullptr, out, nullptr);
}

// round 10
// speedup vs baseline: 5.3267x; 1.0283x over previous
#include <cuda_runtime.h>
#include <cuda_fp16.h>
#include <cstdint>

static constexpr int BSZ = 16384;
static constexpr int HD  = 1024;
static constexpr int DD  = 512;

// ---------------- device scratch (allocation-free contract) ----------------
__device__ __align__(256) __half g_x_h [(size_t)BSZ * DD];
__device__ __align__(256) __half g_h0_h[(size_t)BSZ * HD];
__device__ __align__(256) __half g_h1_h[(size_t)BSZ * HD];
__device__ __align__(256) __half g_w0_h[(size_t)4 * HD * DD];
__device__ __align__(256) __half g_w1_h[(size_t)4 * HD * HD];
__device__ __align__(256) __half g_wd_h[(size_t)DD * HD];

// ---------------- helpers ----------------
__device__ __forceinline__ uint32_t smem_u32(const void* p) {
    uint32_t a;
    asm("{ .reg .u64 t; cvta.to.shared.u64 t, %1; cvt.u32.u64 %0, t; }" : "=r"(a) : "l"(p));
    return a;
}
__device__ __forceinline__ void cpa16(uint32_t dst, const void* src) {
    asm volatile("cp.async.cg.shared.global [%0], [%1], 16;\n" :: "r"(dst), "l"(src));
}
__device__ __forceinline__ void ldsm4(uint32_t* r, uint32_t a) {
    asm volatile("ldmatrix.sync.aligned.m8n8.x4.shared.b16 {%0,%1,%2,%3}, [%4];"
        : "=r"(r[0]), "=r"(r[1]), "=r"(r[2]), "=r"(r[3]) : "r"(a));
}
__device__ __forceinline__ void mma16816(float* d, const uint32_t* a, const uint32_t* b) {
    asm volatile("mma.sync.aligned.m16n8k16.row.col.f32.f16.f16.f32 "
        "{%0,%1,%2,%3}, {%4,%5,%6,%7}, {%8,%9}, {%0,%1,%2,%3};"
        : "+f"(d[0]), "+f"(d[1]), "+f"(d[2]), "+f"(d[3])
        : "r"(a[0]), "r"(a[1]), "r"(a[2]), "r"(a[3]), "r"(b[0]), "r"(b[1]));
}
__device__ __forceinline__ float sigm(float x) { return 1.0f / (1.0f + __expf(-x)); }
__device__ __forceinline__ float tanh_e(float x) {
    float ax = fabsf(x);
    float e  = __expf(2.0f * ax);
    float t  = 1.0f - 2.0f / (1.0f + e);
    return copysignf(t, x);
}

// ---------------- fp32 -> fp16 conversion ----------------
__global__ void cvt_h_kernel(const float4* __restrict__ src, __half2* __restrict__ dst, int n4) {
    int i = blockIdx.x * blockDim.x + threadIdx.x;
    if (i >= n4) return;
    float4 v = src[i];
    dst[2 * i + 0] = __floats2half2_rn(v.x, v.y);
    dst[2 * i + 1] = __floats2half2_rn(v.z, v.w);
}

// ---------------- fused mma.sync GEMM (fp16, 3-stage pipeline, 1 barrier/chunk) ----
// NG==3: gates i/g/o of A @ W^T (f-gate dead), LSTM-cell epilogue -> h (fp16).
// NG==1: decoder A @ W^T + b -> fp32.
template<int K, int NG, int NT>
__global__ void __launch_bounds__(256, 1)
mm_kernel(const __half* __restrict__ Ah, const __half* __restrict__ Wh,
          const float* __restrict__ b0, const float* __restrict__ b1,
          float* __restrict__ outF, __half* __restrict__ outH)
{
    constexpr int PITCH  = 144;              // 64 fp16 + 8 pad -> ldmatrix conflict-free
    constexpr int ASZ    = 128 * PITCH;
    constexpr int WSZ    = NT * PITCH;
    constexpr int STAGE  = ASZ + NG * WSZ;
    constexpr int NSTG   = 3;
    constexpr int NCHUNK = K / 64;
    constexpr int NFRAG  = NT / 16;          // n8 frags per warp per gate (warp spans NT/2)
    constexpr int NPAIR  = NFRAG / 2;

    extern __shared__ char smem[];
    const uint32_t sb = smem_u32(smem);
    float* bs = (float*)(smem + NSTG * STAGE);

    const int tid = threadIdx.x, wid = tid >> 5, lane = tid & 31;
    const int wm = wid & 3, wn = wid >> 2;
    const int row0 = blockIdx.y * 128, col0 = blockIdx.x * NT;

    // bias sums -> smem (consumed only in epilogue; many barriers in between)
    for (int i = tid; i < NG * NT; i += 256) {
        int g = i / NT, n = i - g * NT;
        int go = (NG == 3) ? ((g == 0) ? 0 : (g == 1 ? 2 * HD : 3 * HD)) : 0;
        float bv = b0[go + col0 + n];
        if (NG == 3) bv += b1[go + col0 + n];
        bs[i] = bv;
    }

    const int lr = tid >> 3;     // 0..31 row within 32-row slab
    const int lc = tid & 7;      // 16B chunk within 64-fp16 row

    auto load_chunk = [&](int s, int ck) {
        const int k0 = ck * 64;
        const uint32_t st = sb + s * STAGE;
        #pragma unroll
        for (int it = 0; it < 4; it++) {
            int r = lr + it * 32;
            cpa16(st + r * PITCH + lc * 16, Ah + (size_t)(row0 + r) * K + k0 + lc * 8);
        }
        #pragma unroll
        for (int g = 0; g < NG; g++) {
            const int go = (NG == 3) ? ((g == 0) ? 0 : (g == 1 ? 2 * HD : 3 * HD)) : 0;
            uint32_t wb = st + ASZ + g * WSZ;
            #pragma unroll
            for (int it = 0; it < NT / 32; it++) {
                int r = lr + it * 32;
                cpa16(wb + r * PITCH + lc * 16,
                      Wh + (size_t)(go + col0 + r) * K + k0 + lc * 8);
            }
        }
        asm volatile("cp.async.commit_group;" ::: "memory");
    };

    // ldmatrix per-lane base offsets.
    uint32_t aOff[2];
    #pragma unroll
    for (int f = 0; f < 2; f++)
        aOff[f] = (uint32_t)((wm * 32 + f * 16 + (lane & 15)) * PITCH + (lane >> 4) * 16);
    // W stored [n][k] -> non-trans ldmatrix gives exactly the B fragment (n = l/4, k = 2*(l%4)).
    uint32_t bOff[NPAIR];
    #pragma unroll
    for (int p = 0; p < NPAIR; p++)
        bOff[p] = (uint32_t)((wn * (NT / 2) + p * 16 + (lane & 7) + ((lane >> 4) & 1) * 8) * PITCH
                             + ((lane >> 3) & 1) * 16);

    float acc[NG][2][NFRAG][4];
    #pragma unroll
    for (int g = 0; g < NG; g++)
        #pragma unroll
        for (int f = 0; f < 2; f++)
            #pragma unroll
            for (int j = 0; j < NFRAG; j++)
                #pragma unroll
                for (int q = 0; q < 4; q++) acc[g][f][j][q] = 0.0f;

    load_chunk(0, 0);
    load_chunk(1, 1);

    // 3-stage mainloop, ONE barrier per chunk.
    // iter k: wait(chunk k) -> barrier -> issue load k+2 -> compute k.
    // Overwrite safety: load k+2 targets slot (k-1)%3, last read by compute k-1,
    // which every warp finished before this iteration's barrier.
    for (int k = 0; k < NCHUNK; k++) {
        const int s = k % NSTG;
        if (k + 1 < NCHUNK) asm volatile("cp.async.wait_group 1;" ::: "memory");
        else                asm volatile("cp.async.wait_group 0;" ::: "memory");
        __syncthreads();
        if (k + 2 < NCHUNK) load_chunk((k + 2) % NSTG, k + 2);

        const uint32_t st = sb + s * STAGE;
        #pragma unroll
        for (int ks = 0; ks < 4; ks++) {
            uint32_t aF[2][4];
            ldsm4(aF[0], st + aOff[0] + ks * 32);
            ldsm4(aF[1], st + aOff[1] + ks * 32);
            #pragma unroll
            for (int g = 0; g < NG; g++) {
                const uint32_t wb = st + ASZ + g * WSZ;
                uint32_t bh[NPAIR][4];
                #pragma unroll
                for (int p = 0; p < NPAIR; p++)
                    ldsm4(bh[p], wb + bOff[p] + ks * 32);
                #pragma unroll
                for (int f = 0; f < 2; f++)
                    #pragma unroll
                    for (int j = 0; j < NFRAG; j++)
                        mma16816(acc[g][f][j], aF[f], &bh[j >> 1][(j & 1) * 2]);
            }
        }
    }

    // ---------------- epilogue ----------------
    const int mBase = row0 + wm * 32 + (lane >> 2);
    const int nLoc0 = wn * (NT / 2) + (lane & 3) * 2;      // col offset within tile

    if constexpr (NG == 3) {
        #pragma unroll
        for (int f = 0; f < 2; f++)
            #pragma unroll
            for (int j = 0; j < NFRAG; j++)
                #pragma unroll
                for (int hh = 0; hh < 2; hh++) {
                    int m = mBase + f * 16 + hh * 8;
                    int nl = nLoc0 + j * 8;
                    float h2[2];
                    #pragma unroll
                    for (int u = 0; u < 2; u++) {
                        float iv = sigm(acc[0][f][j][hh * 2 + u] + bs[0 * NT + nl + u]);
                        float gv = tanh_e(acc[1][f][j][hh * 2 + u] + bs[1 * NT + nl + u]);
                        float ov = sigm(acc[2][f][j][hh * 2 + u] + bs[2 * NT + nl + u]);
                        h2[u] = ov * tanh_e(iv * gv);
                    }
                    *(__half2*)(outH + (size_t)m * HD + col0 + nl) = __floats2half2_rn(h2[0], h2[1]);
                }
    } else {
        #pragma unroll
        for (int f = 0; f < 2; f++)
            #pragma unroll
            for (int j = 0; j < NFRAG; j++)
                #pragma unroll
                for (int hh = 0; hh < 2; hh++) {
                    int m = mBase + f * 16 + hh * 8;
                    int nl = nLoc0 + j * 8;
                    float2 v;
                    v.x = acc[0][f][j][hh * 2 + 0] + bs[nl + 0];
                    v.y = acc[0][f][j][hh * 2 + 1] + bs[nl + 1];
                    *(float2*)(outF + (size_t)m * DD + col0 + nl) = v;
                }
    }
}

// ---------------- launch ----------------
extern "C" void kernel_launch(void* const* d_in, const int* in_sizes, int n_in,
                              void* d_out, int out_size) {
    const float* x     = (const float*)d_in[0];
    const float* W_ih0 = (const float*)d_in[1];
    const float* b_ih0 = (const float*)d_in[3];
    const float* b_hh0 = (const float*)d_in[4];
    const float* W_ih1 = (const float*)d_in[5];
    const float* b_ih1 = (const float*)d_in[7];
    const float* b_hh1 = (const float*)d_in[8];
    const float* W_dec = (const float*)d_in[9];
    const float* b_dec = (const float*)d_in[10];
    float* out = (float*)d_out;

    __half *xh, *h0h, *h1h, *w0h, *w1h, *wdh;
    cudaGetSymbolAddress((void**)&xh,  g_x_h);
    cudaGetSymbolAddress((void**)&h0h, g_h0_h);
    cudaGetSymbolAddress((void**)&h1h, g_h1_h);
    cudaGetSymbolAddress((void**)&w0h, g_w0_h);
    cudaGetSymbolAddress((void**)&w1h, g_w1_h);
    cudaGetSymbolAddress((void**)&wdh, g_wd_h);

    // shared-memory sizes (3 stages)
    constexpr int PITCH = 144;
    constexpr int STAGE_L = 128 * PITCH + 3 * 64 * PITCH;     // 46080
    constexpr int STAGE_D = 128 * PITCH + 1 * 128 * PITCH;    // 36864
    constexpr int SM_L = 3 * STAGE_L + 3 * 64 * 4;            // 139008
    constexpr int SM_D = 3 * STAGE_D + 1 * 128 * 4;           // 111104
    cudaFuncSetAttribute(mm_kernel<DD, 3, 64>,  cudaFuncAttributeMaxDynamicSharedMemorySize, SM_L);
    cudaFuncSetAttribute(mm_kernel<HD, 3, 64>,  cudaFuncAttributeMaxDynamicSharedMemorySize, SM_L);
    cudaFuncSetAttribute(mm_kernel<HD, 1, 128>, cudaFuncAttributeMaxDynamicSharedMemorySize, SM_D);

    // conversions (plain fp16)
    auto cvt = [&](const float* src, __half* dst, size_t n) {
        int n4 = (int)(n / 4);
        cvt_h_kernel<<<(n4 + 255) / 256, 256>>>((const float4*)src, (__half2*)dst, n4);
    };
    cvt(x,     xh,  (size_t)BSZ * DD);
    cvt(W_ih0, w0h, (size_t)4 * HD * DD);
    cvt(W_ih1, w1h, (size_t)4 * HD * HD);
    cvt(W_dec, wdh, (size_t)DD * HD);

    dim3 blk(256);
    dim3 gL(HD / 64, BSZ / 128);    // 16 x 128
    dim3 gD(DD / 128, BSZ / 128);   // 4  x 128

    mm_kernel<DD, 3, 64><<<gL, blk, SM_L>>>(xh,  w0h, b_ih0, b_hh0, nullptr, h0h);
    mm_kernel<HD, 3, 64><<<gL, blk, SM_L>>>(h0h, w1h, b_ih1, b_hh1, nullptr, h1h);
    mm_kernel<HD, 1, 128><<<gD, blk, SM_D>>>(h1h, wdh, b_dec, nullptr, out, nullptr);
}

// round 11
// speedup vs baseline: 7.2794x; 1.3666x over previous
#include <cuda_runtime.h>
#include <cuda_fp16.h>
#include <cstdint>

static constexpr int BSZ = 16384;
static constexpr int HD  = 1024;
static constexpr int DD  = 512;

// ---------------- device scratch (allocation-free contract) ----------------
__device__ __align__(256) __half g_x_h [(size_t)BSZ * DD];
__device__ __align__(256) __half g_h0_h[(size_t)BSZ * HD];
__device__ __align__(256) __half g_h1_h[(size_t)BSZ * HD];
__device__ __align__(256) __half g_w0_h[(size_t)4 * HD * DD];
__device__ __align__(256) __half g_w1_h[(size_t)4 * HD * HD];
__device__ __align__(256) __half g_wd_h[(size_t)DD * HD];

// ---------------- helpers ----------------
__device__ __forceinline__ uint32_t smem_u32(const void* p) {
    uint32_t a;
    asm("{ .reg .u64 t; cvta.to.shared.u64 t, %1; cvt.u32.u64 %0, t; }" : "=r"(a) : "l"(p));
    return a;
}
__device__ __forceinline__ void cpa16(uint32_t dst, const void* src) {
    asm volatile("cp.async.cg.shared.global [%0], [%1], 16;\n" :: "r"(dst), "l"(src));
}
__device__ __forceinline__ void ldsm4(uint32_t* r, uint32_t a) {
    asm volatile("ldmatrix.sync.aligned.m8n8.x4.shared.b16 {%0,%1,%2,%3}, [%4];"
        : "=r"(r[0]), "=r"(r[1]), "=r"(r[2]), "=r"(r[3]) : "r"(a));
}
__device__ __forceinline__ void mma16816(float* d, const uint32_t* a, const uint32_t* b) {
    asm volatile("mma.sync.aligned.m16n8k16.row.col.f32.f16.f16.f32 "
        "{%0,%1,%2,%3}, {%4,%5,%6,%7}, {%8,%9}, {%0,%1,%2,%3};"
        : "+f"(d[0]), "+f"(d[1]), "+f"(d[2]), "+f"(d[3])
        : "r"(a[0]), "r"(a[1]), "r"(a[2]), "r"(a[3]), "r"(b[0]), "r"(b[1]));
}
__device__ __forceinline__ float sigm(float x) { return 1.0f / (1.0f + __expf(-x)); }
__device__ __forceinline__ float tanh_e(float x) {
    float ax = fabsf(x);
    float e  = __expf(2.0f * ax);
    float t  = 1.0f - 2.0f / (1.0f + e);
    return copysignf(t, x);
}

// ---------------- fp32 -> fp16 conversion ----------------
__global__ void cvt_h_kernel(const float4* __restrict__ src, __half2* __restrict__ dst, int n4) {
    int i = blockIdx.x * blockDim.x + threadIdx.x;
    if (i >= n4) return;
    float4 v = src[i];
    dst[2 * i + 0] = __floats2half2_rn(v.x, v.y);
    dst[2 * i + 1] = __floats2half2_rn(v.z, v.w);
}

// ---------------- fused mma.sync GEMM (fp16, 2-stage, occ=2 CTAs/SM) ----------
// NG==3: gates i/g/o of A @ W^T (f-gate dead), LSTM-cell epilogue -> h (fp16).
// NG==1: decoder A @ W^T + b -> fp32.
template<int K, int NG, int NT>
__global__ void __launch_bounds__(256, 2)
mm_kernel(const __half* __restrict__ Ah, const __half* __restrict__ Wh,
          const float* __restrict__ b0, const float* __restrict__ b1,
          float* __restrict__ outF, __half* __restrict__ outH)
{
    constexpr int PITCH  = 144;              // 64 fp16 + 8 pad -> ldmatrix conflict-free
    constexpr int ASZ    = 128 * PITCH;
    constexpr int WSZ    = NT * PITCH;
    constexpr int STAGE  = ASZ + NG * WSZ;
    constexpr int NSTG   = 2;
    constexpr int NCHUNK = K / 64;
    constexpr int NFRAG  = NT / 16;          // n8 frags per warp per gate (warp spans NT/2)
    constexpr int NPAIR  = NFRAG / 2;

    extern __shared__ char smem[];
    const uint32_t sb = smem_u32(smem);
    float* bs = (float*)(smem + NSTG * STAGE);

    const int tid = threadIdx.x, wid = tid >> 5, lane = tid & 31;
    const int wm = wid & 3, wn = wid >> 2;
    const int row0 = blockIdx.y * 128, col0 = blockIdx.x * NT;

    // bias sums -> smem (consumed only in epilogue; barriers in between)
    for (int i = tid; i < NG * NT; i += 256) {
        int g = i / NT, n = i - g * NT;
        int go = (NG == 3) ? ((g == 0) ? 0 : (g == 1 ? 2 * HD : 3 * HD)) : 0;
        float bv = b0[go + col0 + n];
        if (NG == 3) bv += b1[go + col0 + n];
        bs[i] = bv;
    }

    const int lr = tid >> 3;     // 0..31 row within 32-row slab
    const int lc = tid & 7;      // 16B chunk within 64-fp16 row

    auto load_chunk = [&](int s, int ck) {
        const int k0 = ck * 64;
        const uint32_t st = sb + s * STAGE;
        #pragma unroll
        for (int it = 0; it < 4; it++) {
            int r = lr + it * 32;
            cpa16(st + r * PITCH + lc * 16, Ah + (size_t)(row0 + r) * K + k0 + lc * 8);
        }
        #pragma unroll
        for (int g = 0; g < NG; g++) {
            const int go = (NG == 3) ? ((g == 0) ? 0 : (g == 1 ? 2 * HD : 3 * HD)) : 0;
            uint32_t wb = st + ASZ + g * WSZ;
            #pragma unroll
            for (int it = 0; it < NT / 32; it++) {
                int r = lr + it * 32;
                cpa16(wb + r * PITCH + lc * 16,
                      Wh + (size_t)(go + col0 + r) * K + k0 + lc * 8);
            }
        }
        asm volatile("cp.async.commit_group;" ::: "memory");
    };

    // ldmatrix per-lane base offsets.
    uint32_t aOff[2];
    #pragma unroll
    for (int f = 0; f < 2; f++)
        aOff[f] = (uint32_t)((wm * 32 + f * 16 + (lane & 15)) * PITCH + (lane >> 4) * 16);
    // W stored [n][k] -> non-trans ldmatrix gives exactly the B fragment (n = l/4, k = 2*(l%4)).
    uint32_t bOff[NPAIR];
    #pragma unroll
    for (int p = 0; p < NPAIR; p++)
        bOff[p] = (uint32_t)((wn * (NT / 2) + p * 16 + (lane & 7) + ((lane >> 4) & 1) * 8) * PITCH
                             + ((lane >> 3) & 1) * 16);

    float acc[NG][2][NFRAG][4];
    #pragma unroll
    for (int g = 0; g < NG; g++)
        #pragma unroll
        for (int f = 0; f < 2; f++)
            #pragma unroll
            for (int j = 0; j < NFRAG; j++)
                #pragma unroll
                for (int q = 0; q < 4; q++) acc[g][f][j][q] = 0.0f;

    load_chunk(0, 0);

    // 2-stage mainloop, ONE barrier per chunk.
    // iter k: wait(chunk k) -> barrier -> issue load k+1 -> compute k.
    // Overwrite safety: load k+1 writes slot (k+1)%2, last read by compute k-1,
    // which every warp finished before this iteration's barrier.
    for (int k = 0; k < NCHUNK; k++) {
        const int s = k % NSTG;
        asm volatile("cp.async.wait_group 0;" ::: "memory");
        __syncthreads();
        if (k + 1 < NCHUNK) load_chunk((k + 1) % NSTG, k + 1);

        const uint32_t st = sb + s * STAGE;
        #pragma unroll
        for (int ks = 0; ks < 4; ks++) {
            uint32_t aF[2][4];
            ldsm4(aF[0], st + aOff[0] + ks * 32);
            ldsm4(aF[1], st + aOff[1] + ks * 32);
            #pragma unroll
            for (int g = 0; g < NG; g++) {
                const uint32_t wb = st + ASZ + g * WSZ;
                uint32_t bh[NPAIR][4];
                #pragma unroll
                for (int p = 0; p < NPAIR; p++)
                    ldsm4(bh[p], wb + bOff[p] + ks * 32);
                #pragma unroll
                for (int f = 0; f < 2; f++)
                    #pragma unroll
                    for (int j = 0; j < NFRAG; j++)
                        mma16816(acc[g][f][j], aF[f], &bh[j >> 1][(j & 1) * 2]);
            }
        }
    }

    // ---------------- epilogue ----------------
    const int mBase = row0 + wm * 32 + (lane >> 2);
    const int nLoc0 = wn * (NT / 2) + (lane & 3) * 2;      // col offset within tile

    if constexpr (NG == 3) {
        #pragma unroll
        for (int f = 0; f < 2; f++)
            #pragma unroll
            for (int j = 0; j < NFRAG; j++)
                #pragma unroll
                for (int hh = 0; hh < 2; hh++) {
                    int m = mBase + f * 16 + hh * 8;
                    int nl = nLoc0 + j * 8;
                    float h2[2];
                    #pragma unroll
                    for (int u = 0; u < 2; u++) {
                        float iv = sigm(acc[0][f][j][hh * 2 + u] + bs[0 * NT + nl + u]);
                        float gv = tanh_e(acc[1][f][j][hh * 2 + u] + bs[1 * NT + nl + u]);
                        float ov = sigm(acc[2][f][j][hh * 2 + u] + bs[2 * NT + nl + u]);
                        h2[u] = ov * tanh_e(iv * gv);
                    }
                    *(__half2*)(outH + (size_t)m * HD + col0 + nl) = __floats2half2_rn(h2[0], h2[1]);
                }
    } else {
        #pragma unroll
        for (int f = 0; f < 2; f++)
            #pragma unroll
            for (int j = 0; j < NFRAG; j++)
                #pragma unroll
                for (int hh = 0; hh < 2; hh++) {
                    int m = mBase + f * 16 + hh * 8;
                    int nl = nLoc0 + j * 8;
                    float2 v;
                    v.x = acc[0][f][j][hh * 2 + 0] + bs[nl + 0];
                    v.y = acc[0][f][j][hh * 2 + 1] + bs[nl + 1];
                    *(float2*)(outF + (size_t)m * DD + col0 + nl) = v;
                }
    }
}

// ---------------- launch ----------------
extern "C" void kernel_launch(void* const* d_in, const int* in_sizes, int n_in,
                              void* d_out, int out_size) {
    const float* x     = (const float*)d_in[0];
    const float* W_ih0 = (const float*)d_in[1];
    const float* b_ih0 = (const float*)d_in[3];
    const float* b_hh0 = (const float*)d_in[4];
    const float* W_ih1 = (const float*)d_in[5];
    const float* b_ih1 = (const float*)d_in[7];
    const float* b_hh1 = (const float*)d_in[8];
    const float* W_dec = (const float*)d_in[9];
    const float* b_dec = (const float*)d_in[10];
    float* out = (float*)d_out;

    __half *xh, *h0h, *h1h, *w0h, *w1h, *wdh;
    cudaGetSymbolAddress((void**)&xh,  g_x_h);
    cudaGetSymbolAddress((void**)&h0h, g_h0_h);
    cudaGetSymbolAddress((void**)&h1h, g_h1_h);
    cudaGetSymbolAddress((void**)&w0h, g_w0_h);
    cudaGetSymbolAddress((void**)&w1h, g_w1_h);
    cudaGetSymbolAddress((void**)&wdh, g_wd_h);

    // shared-memory sizes (2 stages; 2 CTAs/SM: 2 x 92928 = 186 KB < 228 KB)
    constexpr int PITCH = 144;
    constexpr int STAGE_L = 128 * PITCH + 3 * 64 * PITCH;     // 46080
    constexpr int STAGE_D = 128 * PITCH + 1 * 64 * PITCH;     // 27648
    constexpr int SM_L = 2 * STAGE_L + 3 * 64 * 4;            // 92928
    constexpr int SM_D = 2 * STAGE_D + 1 * 64 * 4;            // 55552
    cudaFuncSetAttribute(mm_kernel<DD, 3, 64>,  cudaFuncAttributeMaxDynamicSharedMemorySize, SM_L);
    cudaFuncSetAttribute(mm_kernel<HD, 3, 64>,  cudaFuncAttributeMaxDynamicSharedMemorySize, SM_L);
    cudaFuncSetAttribute(mm_kernel<HD, 1, 64>,  cudaFuncAttributeMaxDynamicSharedMemorySize, SM_D);

    // conversions (plain fp16)
    auto cvt = [&](const float* src, __half* dst, size_t n) {
        int n4 = (int)(n / 4);
        cvt_h_kernel<<<(n4 + 255) / 256, 256>>>((const float4*)src, (__half2*)dst, n4);
    };
    cvt(x,     xh,  (size_t)BSZ * DD);
    cvt(W_ih0, w0h, (size_t)4 * HD * DD);
    cvt(W_ih1, w1h, (size_t)4 * HD * HD);
    cvt(W_dec, wdh, (size_t)DD * HD);

    dim3 blk(256);
    dim3 gL(HD / 64, BSZ / 128);    // 16 x 128
    dim3 gD(DD / 64, BSZ / 128);    // 8  x 128

    mm_kernel<DD, 3, 64><<<gL, blk, SM_L>>>(xh,  w0h, b_ih0, b_hh0, nullptr, h0h);
    mm_kernel<HD, 3, 64><<<gL, blk, SM_L>>>(h0h, w1h, b_ih1, b_hh1, nullptr, h1h);
    mm_kernel<HD, 1, 64><<<gD, blk, SM_D>>>(h1h, wdh, b_dec, nullptr, out, nullptr);
}